// round 1
// baseline (speedup 1.0000x reference)
#include <cuda_runtime.h>

#define B_ 32
#define N_ 524288          // 2^19
#define K_ 16384
#define NBUCK 131072       // rank>>6 buckets over 2^23 rank space
#define EXTRA_CAP 512
#define FBINS 16384        // bins for final per-batch counting sort (bucket id)

// ---------------- static device scratch (no allocation allowed) ----------------
__device__ unsigned           g_ranks[B_ * N_];        // 64 MB
__device__ unsigned           g_hist [B_ * NBUCK];     // 16 MB
__device__ unsigned           g_bstar[B_];
__device__ unsigned           g_base [B_];
__device__ unsigned           g_need [B_];
__device__ unsigned long long g_extras[B_ * EXTRA_CAP];
__device__ int                g_extra_cnt[B_];
__device__ int                g_cand_cnt [B_];
__device__ unsigned long long g_cand[B_ * K_];         // 4 MB

struct KeysParam { unsigned k[2 * B_]; };

// ---------------- threefry2x32, 20 rounds (exact JAX) ----------------
__host__ __device__ __forceinline__ unsigned rotl32(unsigned x, int r) {
#if defined(__CUDA_ARCH__)
    return __funnelshift_l(x, x, r);
#else
    return (x << r) | (x >> (32 - r));
#endif
}

__host__ __device__ __forceinline__ void tf2x32(unsigned k0, unsigned k1,
                                                unsigned x0, unsigned x1,
                                                unsigned& o0, unsigned& o1) {
    unsigned ks2 = k0 ^ k1 ^ 0x1BD11BDAu;
    x0 += k0; x1 += k1;
#define TF_ROUND(r) { x0 += x1; x1 = rotl32(x1, r); x1 ^= x0; }
    TF_ROUND(13) TF_ROUND(15) TF_ROUND(26) TF_ROUND(6)
    x0 += k1;  x1 += ks2 + 1u;
    TF_ROUND(17) TF_ROUND(29) TF_ROUND(16) TF_ROUND(24)
    x0 += ks2; x1 += k0 + 2u;
    TF_ROUND(13) TF_ROUND(15) TF_ROUND(26) TF_ROUND(6)
    x0 += k0;  x1 += k1 + 3u;
    TF_ROUND(17) TF_ROUND(29) TF_ROUND(16) TF_ROUND(24)
    x0 += k1;  x1 += ks2 + 4u;
    TF_ROUND(13) TF_ROUND(15) TF_ROUND(26) TF_ROUND(6)
    x0 += ks2; x1 += k0 + 5u;
#undef TF_ROUND
    o0 = x0; o1 = x1;
}

// ---------------- P0: zero scratch ----------------
__global__ void k_zero() {
    int t = blockIdx.x * blockDim.x + threadIdx.x;
    int stride = gridDim.x * blockDim.x;
    for (int i = t; i < B_ * NBUCK; i += stride) g_hist[i] = 0u;
    if (t < B_) { g_extra_cnt[t] = 0; g_cand_cnt[t] = 0; }
}

// ---------------- P1: validity + threefry rank + fine histogram ----------------
__global__ void k_rank(const float* __restrict__ p, KeysParam keys) {
    unsigned t  = blockIdx.x * blockDim.x + threadIdx.x;   // one thread = 4 points
    unsigned e0 = t * 4u;
    if (e0 >= (unsigned)(B_ * N_)) return;
    unsigned b  = e0 >> 19;
    unsigned i0 = e0 & (N_ - 1);

    const float4* pv = reinterpret_cast<const float4*>(p) + (size_t)t * 3;
    float4 v0 = pv[0], v1 = pv[1], v2 = pv[2];
    float c[12] = { v0.x, v0.y, v0.z, v0.w, v1.x, v1.y,
                    v1.z, v1.w, v2.x, v2.y, v2.z, v2.w };

    unsigned k0 = keys.k[2 * b], k1 = keys.k[2 * b + 1];
    unsigned r[4];
#pragma unroll
    for (int j = 0; j < 4; j++) {
        float s = (c[3 * j] + c[3 * j + 1]) + c[3 * j + 2];   // XLA left-assoc sum
        unsigned a, d;
        tf2x32(k0, k1, 0u, i0 + (unsigned)j, a, d);           // partitionable counter (0, i)
        unsigned bits = a ^ d;                                // 32-bit random_bits
        bool valid = (s != 0.0f);
        r[j] = valid ? (bits >> 9) : 0xFFFFFFFFu;             // uniform order == rank order
        if (valid) atomicAdd(&g_hist[b * NBUCK + (r[j] >> 6)], 1u);
    }
    *reinterpret_cast<uint4*>(&g_ranks[e0]) = make_uint4(r[0], r[1], r[2], r[3]);
}

// ---------------- P2: find boundary bucket per batch ----------------
__global__ void k_findthresh() {
    __shared__ unsigned s[1024];
    int b = blockIdx.x, t = threadIdx.x;
    const unsigned* h = &g_hist[b * NBUCK];
    unsigned sum = 0;
#pragma unroll 4
    for (int j = 0; j < 128; j++) sum += h[t * 128 + j];
    s[t] = sum; __syncthreads();
    for (int off = 1; off < 1024; off <<= 1) {
        unsigned v = (t >= off) ? s[t - off] : 0u;
        __syncthreads();
        s[t] += v;
        __syncthreads();
    }
    unsigned incl = s[t], excl = incl - sum;
    if (excl < (unsigned)K_ && incl >= (unsigned)K_) {      // unique crossing thread
        unsigned cum = excl;
        for (int j = 0; j < 128; j++) {
            unsigned c = h[t * 128 + j];
            if (cum + c >= (unsigned)K_) {
                g_bstar[b] = (unsigned)(t * 128 + j);
                g_base[b]  = cum;
                g_need[b]  = (unsigned)K_ - cum;
                break;
            }
            cum += c;
        }
    }
}

// ---------------- P3: collect sure-selected + boundary-bucket extras ----------------
__global__ void k_collect() {
    unsigned t  = blockIdx.x * blockDim.x + threadIdx.x;
    unsigned e0 = t * 4u;
    if (e0 >= (unsigned)(B_ * N_)) return;
    unsigned b  = e0 >> 19;
    unsigned i0 = e0 & (N_ - 1);
    unsigned bstar = g_bstar[b];

    uint4 rr = *reinterpret_cast<const uint4*>(&g_ranks[e0]);
    unsigned r[4] = { rr.x, rr.y, rr.z, rr.w };
    unsigned long long keys[4];
    int cnt = 0;
#pragma unroll
    for (int j = 0; j < 4; j++) {
        unsigned bin = r[j] >> 6;
        unsigned long long key =
            ((unsigned long long)r[j] << 19) | (unsigned long long)(i0 + j);
        if (bin < bstar) {
            keys[cnt++] = key;
        } else if (bin == bstar) {
            int pos = atomicAdd(&g_extra_cnt[b], 1);
            if (pos < EXTRA_CAP) g_extras[b * EXTRA_CAP + pos] = key;
        }
    }
    // warp-aggregated append (a warp covers 128 consecutive elems: one batch)
    unsigned lane = threadIdx.x & 31u;
    int incl = cnt;
    for (int off = 1; off < 32; off <<= 1) {
        int v = __shfl_up_sync(0xFFFFFFFFu, incl, off);
        if (lane >= (unsigned)off) incl += v;
    }
    int total = __shfl_sync(0xFFFFFFFFu, incl, 31);
    int base = 0;
    if (lane == 31u && total > 0) base = atomicAdd(&g_cand_cnt[b], total);
    base = __shfl_sync(0xFFFFFFFFu, base, 31);
    int off0 = base + incl - cnt;
    for (int j = 0; j < cnt; j++)
        g_cand[(size_t)b * K_ + off0 + j] = keys[j];
}

// ---------------- P4: sort extras, append the `need` smallest ----------------
__global__ void k_extras() {
    __shared__ unsigned long long s[EXTRA_CAP];
    int b = blockIdx.x, t = threadIdx.x;                 // 256 threads
    int cnt = g_extra_cnt[b];
    if (cnt > EXTRA_CAP) cnt = EXTRA_CAP;
    for (int i = t; i < EXTRA_CAP; i += 256)
        s[i] = (i < cnt) ? g_extras[b * EXTRA_CAP + i] : 0xFFFFFFFFFFFFFFFFull;
    __syncthreads();
    for (int k = 2; k <= EXTRA_CAP; k <<= 1) {
        for (int j = k >> 1; j > 0; j >>= 1) {
            for (int i = t; i < EXTRA_CAP; i += 256) {
                int ixj = i ^ j;
                if (ixj > i) {
                    bool up = ((i & k) == 0);
                    unsigned long long a = s[i], c = s[ixj];
                    bool swap = up ? (a > c) : (a < c);
                    if (swap) { s[i] = c; s[ixj] = a; }
                }
            }
            __syncthreads();
        }
    }
    unsigned base = g_base[b], need = g_need[b];
    for (unsigned i = t; i < need; i += 256)
        g_cand[(size_t)b * K_ + base + i] = s[i];
}

// ---------------- P5: per-batch order (counting sort by bucket + per-bin
//                  insertion sort) + gather + write output ----------------
__global__ void k_finalize(const float* __restrict__ p, float* __restrict__ out) {
    extern __shared__ unsigned char smem_raw[];
    unsigned long long* dst  = reinterpret_cast<unsigned long long*>(smem_raw); // 16384
    unsigned*           hist = reinterpret_cast<unsigned*>(dst + K_);           // 16384
    __shared__ unsigned partial[1024];

    int b = blockIdx.x, t = threadIdx.x;                 // 1024 threads
    const unsigned long long* cand = &g_cand[(size_t)b * K_];

#pragma unroll
    for (int r = 0; r < 16; r++) hist[t * 16 + r] = 0u;
    __syncthreads();

#pragma unroll
    for (int r = 0; r < 16; r++) {
        unsigned long long key = cand[t + r * 1024];
        unsigned bin = (unsigned)(key >> 25);            // = rank >> 6
        if (bin > FBINS - 1) bin = FBINS - 1;            // safety (never in practice)
        atomicAdd(&hist[bin], 1u);
    }
    __syncthreads();

    unsigned loc[16], run = 0;
#pragma unroll
    for (int r = 0; r < 16; r++) { loc[r] = run; run += hist[t * 16 + r]; }
    partial[t] = run; __syncthreads();
    for (int off = 1; off < 1024; off <<= 1) {
        unsigned v = (t >= off) ? partial[t - off] : 0u;
        __syncthreads();
        partial[t] += v;
        __syncthreads();
    }
    unsigned chunk_excl = partial[t] - run;
#pragma unroll
    for (int r = 0; r < 16; r++) hist[t * 16 + r] = chunk_excl + loc[r];
    __syncthreads();

#pragma unroll
    for (int r = 0; r < 16; r++) {
        unsigned long long key = cand[t + r * 1024];
        unsigned bin = (unsigned)(key >> 25);
        if (bin > FBINS - 1) bin = FBINS - 1;
        unsigned pos = atomicAdd(&hist[bin], 1u);        // hist becomes inclusive prefix
        dst[pos] = key;
    }
    __syncthreads();

    // per-bin insertion sort (avg ~2.8 elems/bin)
#pragma unroll
    for (int r = 0; r < 16; r++) {
        int bin = t * 16 + r;
        unsigned endp  = hist[bin];
        unsigned start = (bin == 0) ? 0u : hist[bin - 1];
        for (unsigned i = start + 1; i < endp; i++) {
            unsigned long long v = dst[i];
            unsigned j = i;
            while (j > start && dst[j - 1] > v) { dst[j] = dst[j - 1]; j--; }
            dst[j] = v;
        }
    }
    __syncthreads();

    const float* pb = p   + (size_t)b * N_ * 3;
    float*       ob = out + (size_t)b * K_ * 3;
#pragma unroll
    for (int r = 0; r < 16; r++) {
        int j = t + r * 1024;
        unsigned idx = (unsigned)(dst[j] & 0x7FFFFull);
        float x = pb[(size_t)idx * 3 + 0];
        float y = pb[(size_t)idx * 3 + 1];
        float z = pb[(size_t)idx * 3 + 2];
        ob[(size_t)j * 3 + 0] = x;
        ob[(size_t)j * 3 + 1] = y;
        ob[(size_t)j * 3 + 2] = z;
    }
}

// ---------------- launch ----------------
extern "C" void kernel_launch(void* const* d_in, const int* in_sizes, int n_in,
                              void* d_out, int out_size) {
    const float* p = (const float*)d_in[0];
    float* out = (float*)d_out;

    // Exact JAX key derivation (threefry, partitionable mode):
    // master = key(42) -> (0,42); batch key b = TF(master,(0,b));
    // kperm  = split(kb)[0] = TF(kb,(0,0)).
    KeysParam kp;
    for (int b = 0; b < B_; b++) {
        unsigned kb0, kb1, s0, s1;
        tf2x32(0u, 42u, 0u, (unsigned)b, kb0, kb1);
        tf2x32(kb0, kb1, 0u, 0u, s0, s1);
        kp.k[2 * b]     = s0;
        kp.k[2 * b + 1] = s1;
    }

    k_zero<<<2048, 512>>>();
    k_rank<<<(B_ * N_ / 4) / 256, 256>>>(p, kp);
    k_findthresh<<<B_, 1024>>>();
    k_collect<<<(B_ * N_ / 4) / 256, 256>>>();
    k_extras<<<B_, 256>>>();
    cudaFuncSetAttribute(k_finalize, cudaFuncAttributeMaxDynamicSharedMemorySize,
                         K_ * 8 + FBINS * 4);
    k_finalize<<<B_, 1024, K_ * 8 + FBINS * 4>>>(p, out);
}

// round 2
// speedup vs baseline: 1.7484x; 1.7484x over previous
#include <cuda_runtime.h>

#define B_ 32
#define N_ 524288          // 2^19 points per batch
#define K_ 16384
#define T_RANK (1u << 19)  // static candidate threshold on 23-bit rank (E[count]~22.9k)
#define CAP 32768          // per-batch candidate capacity (65 sigma above mean)
#define FBINS 8192         // finalize bins: bin = rank>>6, rank < 2^19
#define EX_CAP 256         // boundary-bin extras capacity

// ---------------- static device scratch ----------------
__device__ int                g_cand_cnt[B_];
__device__ unsigned long long g_cand[B_ * CAP];        // 8 MB

struct KeysParam { unsigned k[2 * B_]; };

// ---------------- threefry2x32, 20 rounds (exact JAX partitionable) ----------------
__host__ __device__ __forceinline__ unsigned rotl32(unsigned x, int r) {
#if defined(__CUDA_ARCH__)
    return __funnelshift_l(x, x, r);
#else
    return (x << r) | (x >> (32 - r));
#endif
}

__host__ __device__ __forceinline__ void tf2x32(unsigned k0, unsigned k1,
                                                unsigned x0, unsigned x1,
                                                unsigned& o0, unsigned& o1) {
    unsigned ks2 = k0 ^ k1 ^ 0x1BD11BDAu;
    x0 += k0; x1 += k1;
#define TF_ROUND(r) { x0 += x1; x1 = rotl32(x1, r); x1 ^= x0; }
    TF_ROUND(13) TF_ROUND(15) TF_ROUND(26) TF_ROUND(6)
    x0 += k1;  x1 += ks2 + 1u;
    TF_ROUND(17) TF_ROUND(29) TF_ROUND(16) TF_ROUND(24)
    x0 += ks2; x1 += k0 + 2u;
    TF_ROUND(13) TF_ROUND(15) TF_ROUND(26) TF_ROUND(6)
    x0 += k0;  x1 += k1 + 3u;
    TF_ROUND(17) TF_ROUND(29) TF_ROUND(16) TF_ROUND(24)
    x0 += k1;  x1 += ks2 + 4u;
    TF_ROUND(13) TF_ROUND(15) TF_ROUND(26) TF_ROUND(6)
    x0 += ks2; x1 += k0 + 5u;
#undef TF_ROUND
    o0 = x0; o1 = x1;
}

// ---------------- P0: zero candidate counters ----------------
__global__ void k_zero() {
    if (threadIdx.x < B_) g_cand_cnt[threadIdx.x] = 0;
}

// ---------------- P1: fused validity + threefry + thresholded collect ----------------
__global__ void k_main(const float* __restrict__ p, KeysParam keys) {
    unsigned t  = blockIdx.x * blockDim.x + threadIdx.x;   // one thread = 4 points
    unsigned e0 = t * 4u;
    unsigned b  = e0 >> 19;
    unsigned i0 = e0 & (N_ - 1);

    const float4* pv = reinterpret_cast<const float4*>(p) + (size_t)t * 3;
    float4 v0 = pv[0], v1 = pv[1], v2 = pv[2];
    float c[12] = { v0.x, v0.y, v0.z, v0.w, v1.x, v1.y,
                    v1.z, v1.w, v2.x, v2.y, v2.z, v2.w };

    unsigned k0 = keys.k[2 * b], k1 = keys.k[2 * b + 1];

    unsigned rank[4];
    bool cand[4];
#pragma unroll
    for (int j = 0; j < 4; j++) {
        float s = (c[3 * j] + c[3 * j + 1]) + c[3 * j + 2];   // XLA left-assoc sum
        unsigned a, d;
        tf2x32(k0, k1, 0u, i0 + (unsigned)j, a, d);           // counter (0, i)
        rank[j] = (a ^ d) >> 9;                               // 23-bit rank
        cand[j] = (s != 0.0f) && (rank[j] < T_RANK);
    }

    // warp-aggregated append (warp = 128 consecutive elems -> single batch)
    unsigned lane = threadIdx.x & 31u;
    unsigned lt_mask = (1u << lane) - 1u;
    unsigned msk[4];
    int tot = 0;
#pragma unroll
    for (int j = 0; j < 4; j++) {
        msk[j] = __ballot_sync(0xFFFFFFFFu, cand[j]);
        tot += __popc(msk[j]);
    }
    int base = 0;
    if (lane == 0 && tot > 0) base = atomicAdd(&g_cand_cnt[b], tot);
    base = __shfl_sync(0xFFFFFFFFu, base, 0);
    int running = base;
#pragma unroll
    for (int j = 0; j < 4; j++) {
        if (cand[j]) {
            int pos = running + __popc(msk[j] & lt_mask);
            if (pos < CAP)
                g_cand[(size_t)b * CAP + pos] =
                    ((unsigned long long)rank[j] << 19) | (unsigned long long)(i0 + j);
        }
        running += __popc(msk[j]);
    }
}

// ---------------- P2: per-batch exact selection + order + gather ----------------
__global__ void k_final(const float* __restrict__ p, float* __restrict__ out) {
    extern __shared__ unsigned char smem_raw[];
    unsigned long long* dst  = reinterpret_cast<unsigned long long*>(smem_raw); // K_ keys (128KB)
    unsigned*           offs = reinterpret_cast<unsigned*>(dst + K_);           // FBINS (32KB)
    __shared__ unsigned partial[1024];
    __shared__ unsigned long long extras[EX_CAP];
    __shared__ int  s_ecnt;
    __shared__ unsigned s_bstar, s_base, s_need;

    int b = blockIdx.x, t = threadIdx.x;                 // 1024 threads
    const unsigned long long* cand = &g_cand[(size_t)b * CAP];
    int C = g_cand_cnt[b]; if (C > CAP) C = CAP;

    if (t == 0) s_ecnt = 0;
#pragma unroll
    for (int r = 0; r < FBINS / 1024; r++) offs[t + r * 1024] = 0u;
    __syncthreads();

    // pass 1: histogram over bins (bin = rank>>6 = key>>25)
    for (int i = t; i < C; i += 1024) {
        unsigned bin = (unsigned)(cand[i] >> 25);
        atomicAdd(&offs[bin], 1u);
    }
    __syncthreads();

    // block scan over FBINS (8 bins/thread)
    unsigned loc[FBINS / 1024], run = 0;
#pragma unroll
    for (int r = 0; r < FBINS / 1024; r++) { loc[r] = run; run += offs[t * (FBINS / 1024) + r]; }
    partial[t] = run; __syncthreads();
    for (int off = 1; off < 1024; off <<= 1) {
        unsigned v = (t >= off) ? partial[t - off] : 0u;
        __syncthreads();
        partial[t] += v;
        __syncthreads();
    }
    unsigned incl = partial[t], excl = incl - run;
    // find exact K-crossing bin
    if (excl < (unsigned)K_ && incl >= (unsigned)K_) {
        unsigned cum = excl;
#pragma unroll
        for (int r = 0; r < FBINS / 1024; r++) {
            unsigned cc = offs[t * (FBINS / 1024) + r];
            if (cum + cc >= (unsigned)K_) {
                s_bstar = (unsigned)(t * (FBINS / 1024) + r);
                s_base  = cum;
                s_need  = (unsigned)K_ - cum;
                break;
            }
            cum += cc;
        }
    }
    // convert offs to global exclusive offsets
    unsigned chunk_excl = excl;
#pragma unroll
    for (int r = 0; r < FBINS / 1024; r++) offs[t * (FBINS / 1024) + r] = chunk_excl + loc[r];
    __syncthreads();

    unsigned bstar = s_bstar, base = s_base, need = s_need;

    // pass 2: scatter sure-selected, stash boundary-bin extras
    for (int i = t; i < C; i += 1024) {
        unsigned long long key = cand[i];
        unsigned bin = (unsigned)(key >> 25);
        if (bin < bstar) {
            unsigned pos = atomicAdd(&offs[bin], 1u);    // offs -> inclusive prefix
            dst[pos] = key;
        } else if (bin == bstar) {
            int ep = atomicAdd(&s_ecnt, 1);
            if (ep < EX_CAP) extras[ep] = key;
        }
    }
    __syncthreads();

    // sort extras (bitonic over EX_CAP), append `need` smallest at base
    int ec = s_ecnt; if (ec > EX_CAP) ec = EX_CAP;
    if (t < EX_CAP && t >= ec) extras[t] = 0xFFFFFFFFFFFFFFFFull;
    __syncthreads();
    for (int k = 2; k <= EX_CAP; k <<= 1) {
        for (int j = k >> 1; j > 0; j >>= 1) {
            if (t < EX_CAP) {
                int ixj = t ^ j;
                if (ixj > t) {
                    bool up = ((t & k) == 0);
                    unsigned long long a = extras[t], cc = extras[ixj];
                    if (up ? (a > cc) : (a < cc)) { extras[t] = cc; extras[ixj] = a; }
                }
            }
            __syncthreads();
        }
    }
    if (t < (int)need) dst[base + t] = extras[t];        // need <= bin count <= EX_CAP check
    for (unsigned i = 1024 + t; i < need; i += 1024) dst[base + i] = extras[i];
    __syncthreads();

    // per-bin insertion sort over [0, base) (avg ~2.8 elems/bin)
#pragma unroll
    for (int r = 0; r < FBINS / 1024; r++) {
        unsigned bin = (unsigned)t * (FBINS / 1024) + r;
        if (bin < bstar) {
            unsigned endp  = offs[bin];                  // inclusive prefix
            unsigned start = (bin == 0) ? 0u : offs[bin - 1];
            for (unsigned i = start + 1; i < endp; i++) {
                unsigned long long v = dst[i];
                unsigned jj = i;
                while (jj > start && dst[jj - 1] > v) { dst[jj] = dst[jj - 1]; jj--; }
                dst[jj] = v;
            }
        }
    }
    __syncthreads();

    // gather + write
    const float* pb = p   + (size_t)b * N_ * 3;
    float*       ob = out + (size_t)b * K_ * 3;
#pragma unroll
    for (int r = 0; r < K_ / 1024; r++) {
        int j = t + r * 1024;
        unsigned idx = (unsigned)(dst[j] & 0x7FFFFull);
        float x = __ldg(&pb[(size_t)idx * 3 + 0]);
        float y = __ldg(&pb[(size_t)idx * 3 + 1]);
        float z = __ldg(&pb[(size_t)idx * 3 + 2]);
        ob[(size_t)j * 3 + 0] = x;
        ob[(size_t)j * 3 + 1] = y;
        ob[(size_t)j * 3 + 2] = z;
    }
}

// ---------------- launch ----------------
extern "C" void kernel_launch(void* const* d_in, const int* in_sizes, int n_in,
                              void* d_out, int out_size) {
    const float* p = (const float*)d_in[0];
    float* out = (float*)d_out;

    // Exact JAX key derivation (threefry, partitionable mode)
    KeysParam kp;
    for (int b = 0; b < B_; b++) {
        unsigned kb0, kb1, s0, s1;
        tf2x32(0u, 42u, 0u, (unsigned)b, kb0, kb1);
        tf2x32(kb0, kb1, 0u, 0u, s0, s1);
        kp.k[2 * b]     = s0;
        kp.k[2 * b + 1] = s1;
    }

    k_zero<<<1, 32>>>();
    k_main<<<(B_ * N_ / 4) / 256, 256>>>(p, kp);
    cudaFuncSetAttribute(k_final, cudaFuncAttributeMaxDynamicSharedMemorySize,
                         K_ * 8 + FBINS * 4);
    k_final<<<B_, 1024, K_ * 8 + FBINS * 4>>>(p, out);
}

// round 3
// speedup vs baseline: 4.3184x; 2.4699x over previous
#include <cuda_runtime.h>

#define B_ 32
#define N_ 524288          // 2^19 points per batch
#define K_ 16384
#define T_RANK (1u << 19)  // static candidate threshold on 23-bit rank (E[count]~22.9k)
#define CAP 32768          // per-batch candidate capacity
#define FBINS 8192         // order bins: bin = rank>>6, rank < 2^19
#define EX_CAP 256         // boundary-bin extras capacity

// ---------------- static device scratch ----------------
__device__ int                g_cand_cnt[B_];          // zero-init at load; reset by k_order
__device__ unsigned long long g_cand[B_ * CAP];        // 8 MB
__device__ unsigned           g_sel [B_ * K_];         // ordered selected indices (2 MB)

struct KeysParam { unsigned k[2 * B_]; };

// ---------------- threefry2x32, 20 rounds (exact JAX partitionable) ----------------
__host__ __device__ __forceinline__ unsigned rotl32(unsigned x, int r) {
#if defined(__CUDA_ARCH__)
    return __funnelshift_l(x, x, r);
#else
    return (x << r) | (x >> (32 - r));
#endif
}

__host__ __device__ __forceinline__ void tf2x32(unsigned k0, unsigned k1,
                                                unsigned x0, unsigned x1,
                                                unsigned& o0, unsigned& o1) {
    unsigned ks2 = k0 ^ k1 ^ 0x1BD11BDAu;
    x0 += k0; x1 += k1;
#define TF_ROUND(r) { x0 += x1; x1 = rotl32(x1, r); x1 ^= x0; }
    TF_ROUND(13) TF_ROUND(15) TF_ROUND(26) TF_ROUND(6)
    x0 += k1;  x1 += ks2 + 1u;
    TF_ROUND(17) TF_ROUND(29) TF_ROUND(16) TF_ROUND(24)
    x0 += ks2; x1 += k0 + 2u;
    TF_ROUND(13) TF_ROUND(15) TF_ROUND(26) TF_ROUND(6)
    x0 += k0;  x1 += k1 + 3u;
    TF_ROUND(17) TF_ROUND(29) TF_ROUND(16) TF_ROUND(24)
    x0 += k1;  x1 += ks2 + 4u;
    TF_ROUND(13) TF_ROUND(15) TF_ROUND(26) TF_ROUND(6)
    x0 += ks2; x1 += k0 + 5u;
#undef TF_ROUND
    o0 = x0; o1 = x1;
}

// ---------------- P1: fused validity + threefry + thresholded collect ----------------
__global__ void k_main(const float* __restrict__ p, KeysParam keys) {
    __shared__ int s_woff[8];
    __shared__ int s_base;

    unsigned t  = blockIdx.x * blockDim.x + threadIdx.x;   // one thread = 4 points
    unsigned e0 = t * 4u;                                  // block = 1024 consec elems -> one batch
    unsigned b  = e0 >> 19;
    unsigned i0 = e0 & (N_ - 1);

    const float4* pv = reinterpret_cast<const float4*>(p) + (size_t)t * 3;
    float4 v0 = pv[0], v1 = pv[1], v2 = pv[2];
    float c[12] = { v0.x, v0.y, v0.z, v0.w, v1.x, v1.y,
                    v1.z, v1.w, v2.x, v2.y, v2.z, v2.w };

    unsigned k0 = keys.k[2 * b], k1 = keys.k[2 * b + 1];

    unsigned rank[4];
    bool cand[4];
#pragma unroll
    for (int j = 0; j < 4; j++) {
        float s = (c[3 * j] + c[3 * j + 1]) + c[3 * j + 2];   // XLA left-assoc sum
        unsigned a, d;
        tf2x32(k0, k1, 0u, i0 + (unsigned)j, a, d);           // counter (0, i)
        rank[j] = (a ^ d) >> 9;                               // 23-bit rank
        cand[j] = (s != 0.0f) && (rank[j] < T_RANK);
    }

    // ---- hierarchical append: warp ballots -> block reduce -> ONE global atomic ----
    unsigned lane = threadIdx.x & 31u;
    unsigned wid  = threadIdx.x >> 5;                      // 0..7
    unsigned lt_mask = (1u << lane) - 1u;
    unsigned msk[4];
    int tot = 0;
#pragma unroll
    for (int j = 0; j < 4; j++) {
        msk[j] = __ballot_sync(0xFFFFFFFFu, cand[j]);
        tot += __popc(msk[j]);
    }
    if (lane == 0) s_woff[wid] = tot;
    __syncthreads();
    if (threadIdx.x == 0) {
        int sum = 0;
#pragma unroll
        for (int w = 0; w < 8; w++) { int cc = s_woff[w]; s_woff[w] = sum; sum += cc; }
        s_base = atomicAdd(&g_cand_cnt[b], sum);
    }
    __syncthreads();
    int running = s_base + s_woff[wid];
#pragma unroll
    for (int j = 0; j < 4; j++) {
        if (cand[j]) {
            int pos = running + __popc(msk[j] & lt_mask);
            if (pos < CAP)
                g_cand[(size_t)b * CAP + pos] =
                    ((unsigned long long)rank[j] << 19) | (unsigned long long)(i0 + j);
        }
        running += __popc(msk[j]);
    }
}

// ---------------- P2: per-batch exact selection + full ordering (keys only) ----------------
__global__ void k_order() {
    extern __shared__ unsigned char smem_raw[];
    unsigned long long* dst  = reinterpret_cast<unsigned long long*>(smem_raw); // K_ (128KB)
    unsigned*           offs = reinterpret_cast<unsigned*>(dst + K_);           // FBINS (32KB)
    __shared__ unsigned s_wsum[32];
    __shared__ unsigned long long extras[EX_CAP];
    __shared__ int  s_ecnt;
    __shared__ unsigned s_bstar, s_base, s_need;

    int b = blockIdx.x, t = threadIdx.x;                 // 1024 threads
    unsigned lane = t & 31u, wid = t >> 5;
    const unsigned long long* cand = &g_cand[(size_t)b * CAP];
    int C = g_cand_cnt[b]; if (C > CAP) C = CAP;

    if (t == 0) s_ecnt = 0;
#pragma unroll
    for (int r = 0; r < FBINS / 1024; r++) offs[t + r * 1024] = 0u;
    __syncthreads();

    // pass 1: histogram (bin = key>>25 = rank>>6)
    for (int i = t; i < C; i += 1024)
        atomicAdd(&offs[(unsigned)(cand[i] >> 25)], 1u);
    __syncthreads();

    // block scan over FBINS (8 bins/thread) via shuffle scan
    unsigned loc[FBINS / 1024], run = 0;
#pragma unroll
    for (int r = 0; r < FBINS / 1024; r++) { loc[r] = run; run += offs[t * (FBINS / 1024) + r]; }
    unsigned wincl = run;
    for (int off = 1; off < 32; off <<= 1) {
        unsigned v = __shfl_up_sync(0xFFFFFFFFu, wincl, off);
        if (lane >= (unsigned)off) wincl += v;
    }
    if (lane == 31u) s_wsum[wid] = wincl;
    __syncthreads();
    if (wid == 0) {
        unsigned v = s_wsum[lane];
        unsigned sc = v;
        for (int off = 1; off < 32; off <<= 1) {
            unsigned u = __shfl_up_sync(0xFFFFFFFFu, sc, off);
            if (lane >= (unsigned)off) sc += u;
        }
        s_wsum[lane] = sc - v;                           // exclusive warp bases
    }
    __syncthreads();
    unsigned incl = wincl + s_wsum[wid];
    unsigned excl = incl - run;

    // exact K-crossing bin
    if (excl < (unsigned)K_ && incl >= (unsigned)K_) {
        unsigned cum = excl;
#pragma unroll
        for (int r = 0; r < FBINS / 1024; r++) {
            unsigned cc = offs[t * (FBINS / 1024) + r];
            if (cum + cc >= (unsigned)K_) {
                s_bstar = (unsigned)(t * (FBINS / 1024) + r);
                s_base  = cum;
                s_need  = (unsigned)K_ - cum;
                break;
            }
            cum += cc;
        }
    }
#pragma unroll
    for (int r = 0; r < FBINS / 1024; r++) offs[t * (FBINS / 1024) + r] = excl + loc[r];
    __syncthreads();

    unsigned bstar = s_bstar, base = s_base, need = s_need;

    // pass 2: scatter sure-selected, stash boundary-bin extras
    for (int i = t; i < C; i += 1024) {
        unsigned long long key = cand[i];
        unsigned bin = (unsigned)(key >> 25);
        if (bin < bstar) {
            unsigned pos = atomicAdd(&offs[bin], 1u);    // offs -> inclusive prefix
            dst[pos] = key;
        } else if (bin == bstar) {
            int ep = atomicAdd(&s_ecnt, 1);
            if (ep < EX_CAP) extras[ep] = key;
        }
    }
    __syncthreads();

    // sort extras (bitonic), append `need` smallest at base
    int ec = s_ecnt; if (ec > EX_CAP) ec = EX_CAP;
    if (t < EX_CAP && t >= ec) extras[t] = 0xFFFFFFFFFFFFFFFFull;
    __syncthreads();
    for (int k = 2; k <= EX_CAP; k <<= 1) {
        for (int j = k >> 1; j > 0; j >>= 1) {
            if (t < EX_CAP) {
                int ixj = t ^ j;
                if (ixj > t) {
                    bool up = ((t & k) == 0);
                    unsigned long long a = extras[t], cc = extras[ixj];
                    if (up ? (a > cc) : (a < cc)) { extras[t] = cc; extras[ixj] = a; }
                }
            }
            __syncthreads();
        }
    }
    if (t < (int)need) dst[base + t] = extras[t];
    __syncthreads();

    // per-bin insertion sort (avg ~2.8 elems/bin)
#pragma unroll
    for (int r = 0; r < FBINS / 1024; r++) {
        unsigned bin = (unsigned)t * (FBINS / 1024) + r;
        if (bin < bstar) {
            unsigned endp  = offs[bin];
            unsigned start = (bin == 0) ? 0u : offs[bin - 1];
            for (unsigned i = start + 1; i < endp; i++) {
                unsigned long long v = dst[i];
                unsigned jj = i;
                while (jj > start && dst[jj - 1] > v) { dst[jj] = dst[jj - 1]; jj--; }
                dst[jj] = v;
            }
        }
    }
    __syncthreads();

    // emit ordered indices; reset counter for next graph replay
    unsigned* sel = &g_sel[(size_t)b * K_];
#pragma unroll
    for (int r = 0; r < K_ / 1024; r++) {
        int j = t + r * 1024;
        sel[j] = (unsigned)(dst[j] & 0x7FFFFull);
    }
    if (t == 0) g_cand_cnt[b] = 0;
}

// ---------------- P3: full-chip gather ----------------
__global__ void k_gather(const float* __restrict__ p, float* __restrict__ out) {
    int j = blockIdx.x * blockDim.x + threadIdx.x;       // one thread = one output point
    int b = j >> 14;                                     // K_ = 2^14
    unsigned idx = g_sel[j];
    const float* src = p + ((size_t)b * N_ + idx) * 3;
    float x = __ldg(src + 0);
    float y = __ldg(src + 1);
    float z = __ldg(src + 2);
    float* dst = out + (size_t)j * 3;
    dst[0] = x; dst[1] = y; dst[2] = z;
}

// ---------------- launch ----------------
extern "C" void kernel_launch(void* const* d_in, const int* in_sizes, int n_in,
                              void* d_out, int out_size) {
    const float* p = (const float*)d_in[0];
    float* out = (float*)d_out;

    // Exact JAX key derivation (threefry, partitionable mode)
    KeysParam kp;
    for (int b = 0; b < B_; b++) {
        unsigned kb0, kb1, s0, s1;
        tf2x32(0u, 42u, 0u, (unsigned)b, kb0, kb1);
        tf2x32(kb0, kb1, 0u, 0u, s0, s1);
        kp.k[2 * b]     = s0;
        kp.k[2 * b + 1] = s1;
    }

    k_main<<<(B_ * N_ / 4) / 256, 256>>>(p, kp);
    cudaFuncSetAttribute(k_order, cudaFuncAttributeMaxDynamicSharedMemorySize,
                         K_ * 8 + FBINS * 4);
    k_order<<<B_, 1024, K_ * 8 + FBINS * 4>>>();
    k_gather<<<(B_ * K_) / 256, 256>>>(p, out);
}

// round 4
// speedup vs baseline: 4.3293x; 1.0025x over previous
#include <cuda_runtime.h>

#define B_ 32
#define N_ 524288          // 2^19 points per batch
#define K_ 16384
#define T_RANK (1u << 19)  // static candidate threshold on 23-bit rank (E[count]~22.9k)
#define CAP 32768          // per-batch candidate capacity
#define FBINS 8192         // order bins: bin = rank>>6, rank < 2^19
#define EX_CAP 64          // boundary-bin extras capacity (bin ~ Poisson(2.8), >20 sigma)

// ---------------- static device scratch ----------------
__device__ int                g_cand_cnt[B_];          // zero-init at load; reset by k_order
__device__ unsigned long long g_cand[B_ * CAP];        // 8 MB
__device__ unsigned           g_sel [B_ * K_];         // ordered selected indices (2 MB)

struct KeysParam { unsigned k[2 * B_]; unsigned one; };

// ---------------- threefry2x32, 20 rounds (exact JAX partitionable) ----------------
__host__ __device__ __forceinline__ unsigned rotl32(unsigned x, int r) {
#if defined(__CUDA_ARCH__)
    return __funnelshift_l(x, x, r);
#else
    return (x << r) | (x >> (32 - r));
#endif
}

// fma-pipe add: IMAD(a, one, b) with `one` opaque at compile time.
__device__ __forceinline__ unsigned addf(unsigned a, unsigned one, unsigned b) {
    unsigned d;
    asm("mad.lo.u32 %0, %1, %2, %3;" : "=r"(d) : "r"(a), "r"(one), "r"(b));
    return d;
}

// host-side reference version (plain adds)
__host__ __forceinline__ void tf2x32_host(unsigned k0, unsigned k1,
                                          unsigned x0, unsigned x1,
                                          unsigned& o0, unsigned& o1) {
    unsigned ks2 = k0 ^ k1 ^ 0x1BD11BDAu;
    x0 += k0; x1 += k1;
#define TF_ROUND(r) { x0 += x1; x1 = (x1 << r) | (x1 >> (32 - r)); x1 ^= x0; }
    TF_ROUND(13) TF_ROUND(15) TF_ROUND(26) TF_ROUND(6)
    x0 += k1;  x1 += ks2 + 1u;
    TF_ROUND(17) TF_ROUND(29) TF_ROUND(16) TF_ROUND(24)
    x0 += ks2; x1 += k0 + 2u;
    TF_ROUND(13) TF_ROUND(15) TF_ROUND(26) TF_ROUND(6)
    x0 += k0;  x1 += k1 + 3u;
    TF_ROUND(17) TF_ROUND(29) TF_ROUND(16) TF_ROUND(24)
    x0 += k1;  x1 += ks2 + 4u;
    TF_ROUND(13) TF_ROUND(15) TF_ROUND(26) TF_ROUND(6)
    x0 += ks2; x1 += k0 + 5u;
#undef TF_ROUND
    o0 = x0; o1 = x1;
}

// device version: every add forced onto the fma pipe (IMAD) to balance against
// the alu-pipe-forced SHF/LOP3.
__device__ __forceinline__ unsigned tf2x32_bits(unsigned k0, unsigned k1,
                                                unsigned ks2, unsigned x1in,
                                                unsigned one) {
    // x0 starts at 0, so first injection: x0 = k0, x1 = x1in + k1
    unsigned x0 = k0;
    unsigned x1 = addf(x1in, one, k1);
#define TF_ROUND(r) { x0 = addf(x0, one, x1); x1 = rotl32(x1, r); x1 ^= x0; }
    TF_ROUND(13) TF_ROUND(15) TF_ROUND(26) TF_ROUND(6)
    x0 = addf(x0, one, k1);  x1 = addf(x1, one, ks2 + 1u);
    TF_ROUND(17) TF_ROUND(29) TF_ROUND(16) TF_ROUND(24)
    x0 = addf(x0, one, ks2); x1 = addf(x1, one, k0 + 2u);
    TF_ROUND(13) TF_ROUND(15) TF_ROUND(26) TF_ROUND(6)
    x0 = addf(x0, one, k0);  x1 = addf(x1, one, k1 + 3u);
    TF_ROUND(17) TF_ROUND(29) TF_ROUND(16) TF_ROUND(24)
    x0 = addf(x0, one, k1);  x1 = addf(x1, one, ks2 + 4u);
    TF_ROUND(13) TF_ROUND(15) TF_ROUND(26) TF_ROUND(6)
    x0 = addf(x0, one, ks2); x1 = addf(x1, one, k0 + 5u);
#undef TF_ROUND
    return x0 ^ x1;
}

// ---------------- P1: fused validity + threefry + thresholded collect ----------------
__global__ void k_main(const float* __restrict__ p, KeysParam keys) {
    __shared__ int s_woff[8];
    __shared__ int s_base;

    unsigned t  = blockIdx.x * blockDim.x + threadIdx.x;   // one thread = 4 points
    unsigned e0 = t * 4u;                                  // block = 1024 consec elems -> one batch
    unsigned b  = e0 >> 19;
    unsigned i0 = e0 & (N_ - 1);
    unsigned one = keys.one;                               // == 1, opaque

    const float4* pv = reinterpret_cast<const float4*>(p) + (size_t)t * 3;
    float4 v0 = pv[0], v1 = pv[1], v2 = pv[2];
    float c[12] = { v0.x, v0.y, v0.z, v0.w, v1.x, v1.y,
                    v1.z, v1.w, v2.x, v2.y, v2.z, v2.w };

    unsigned k0 = keys.k[2 * b], k1 = keys.k[2 * b + 1];
    unsigned ks2 = k0 ^ k1 ^ 0x1BD11BDAu;

    unsigned rank[4];
    bool cand[4];
#pragma unroll
    for (int j = 0; j < 4; j++) {
        float s = (c[3 * j] + c[3 * j + 1]) + c[3 * j + 2];   // XLA left-assoc sum
        unsigned bits = tf2x32_bits(k0, k1, ks2, i0 + (unsigned)j, one);
        rank[j] = bits >> 9;                                  // 23-bit rank
        cand[j] = (s != 0.0f) && (rank[j] < T_RANK);
    }

    // ---- hierarchical append: warp ballots -> block reduce -> ONE global atomic ----
    unsigned lane = threadIdx.x & 31u;
    unsigned wid  = threadIdx.x >> 5;                      // 0..7
    unsigned lt_mask = (1u << lane) - 1u;
    unsigned msk[4];
    int tot = 0;
#pragma unroll
    for (int j = 0; j < 4; j++) {
        msk[j] = __ballot_sync(0xFFFFFFFFu, cand[j]);
        tot += __popc(msk[j]);
    }
    if (lane == 0) s_woff[wid] = tot;
    __syncthreads();
    if (threadIdx.x == 0) {
        int sum = 0;
#pragma unroll
        for (int w = 0; w < 8; w++) { int cc = s_woff[w]; s_woff[w] = sum; sum += cc; }
        s_base = atomicAdd(&g_cand_cnt[b], sum);
    }
    __syncthreads();
    int running = s_base + s_woff[wid];
#pragma unroll
    for (int j = 0; j < 4; j++) {
        if (cand[j]) {
            int pos = running + __popc(msk[j] & lt_mask);
            if (pos < CAP)
                g_cand[(size_t)b * CAP + pos] =
                    ((unsigned long long)rank[j] << 19) | (unsigned long long)(i0 + j);
        }
        running += __popc(msk[j]);
    }
}

// ---------------- P2: per-batch exact selection + full ordering (keys only) ----------------
__global__ void k_order() {
    extern __shared__ unsigned char smem_raw[];
    unsigned long long* dst  = reinterpret_cast<unsigned long long*>(smem_raw); // K_ (128KB)
    unsigned*           offs = reinterpret_cast<unsigned*>(dst + K_);           // FBINS (32KB)
    __shared__ unsigned s_wsum[32];
    __shared__ unsigned long long extras[EX_CAP];
    __shared__ int  s_ecnt;
    __shared__ unsigned s_bstar, s_base, s_need;

    int b = blockIdx.x, t = threadIdx.x;                 // 1024 threads
    unsigned lane = t & 31u, wid = t >> 5;
    const unsigned long long* cand = &g_cand[(size_t)b * CAP];
    int C = g_cand_cnt[b]; if (C > CAP) C = CAP;

    if (t == 0) s_ecnt = 0;
#pragma unroll
    for (int r = 0; r < FBINS / 1024; r++) offs[t + r * 1024] = 0u;
    __syncthreads();

    // pass 1: histogram (bin = key>>25 = rank>>6)
    for (int i = t; i < C; i += 1024)
        atomicAdd(&offs[(unsigned)(cand[i] >> 25)], 1u);
    __syncthreads();

    // block scan over FBINS (8 bins/thread) via shuffle scan
    unsigned loc[FBINS / 1024], run = 0;
#pragma unroll
    for (int r = 0; r < FBINS / 1024; r++) { loc[r] = run; run += offs[t * (FBINS / 1024) + r]; }
    unsigned wincl = run;
    for (int off = 1; off < 32; off <<= 1) {
        unsigned v = __shfl_up_sync(0xFFFFFFFFu, wincl, off);
        if (lane >= (unsigned)off) wincl += v;
    }
    if (lane == 31u) s_wsum[wid] = wincl;
    __syncthreads();
    if (wid == 0) {
        unsigned v = s_wsum[lane];
        unsigned sc = v;
        for (int off = 1; off < 32; off <<= 1) {
            unsigned u = __shfl_up_sync(0xFFFFFFFFu, sc, off);
            if (lane >= (unsigned)off) sc += u;
        }
        s_wsum[lane] = sc - v;                           // exclusive warp bases
    }
    __syncthreads();
    unsigned incl = wincl + s_wsum[wid];
    unsigned excl = incl - run;

    // exact K-crossing bin
    if (excl < (unsigned)K_ && incl >= (unsigned)K_) {
        unsigned cum = excl;
#pragma unroll
        for (int r = 0; r < FBINS / 1024; r++) {
            unsigned cc = offs[t * (FBINS / 1024) + r];
            if (cum + cc >= (unsigned)K_) {
                s_bstar = (unsigned)(t * (FBINS / 1024) + r);
                s_base  = cum;
                s_need  = (unsigned)K_ - cum;
                break;
            }
            cum += cc;
        }
    }
#pragma unroll
    for (int r = 0; r < FBINS / 1024; r++) offs[t * (FBINS / 1024) + r] = excl + loc[r];
    __syncthreads();

    unsigned bstar = s_bstar, base = s_base, need = s_need;

    // pass 2: scatter sure-selected, stash boundary-bin extras
    for (int i = t; i < C; i += 1024) {
        unsigned long long key = cand[i];
        unsigned bin = (unsigned)(key >> 25);
        if (bin < bstar) {
            unsigned pos = atomicAdd(&offs[bin], 1u);    // offs -> inclusive prefix
            dst[pos] = key;
        } else if (bin == bstar) {
            int ep = atomicAdd(&s_ecnt, 1);
            if (ep < EX_CAP) extras[ep] = key;
        }
    }
    __syncthreads();

    // sort extras (bitonic over EX_CAP), append `need` smallest at base
    int ec = s_ecnt; if (ec > EX_CAP) ec = EX_CAP;
    if (t < EX_CAP && t >= ec) extras[t] = 0xFFFFFFFFFFFFFFFFull;
    __syncthreads();
    for (int k = 2; k <= EX_CAP; k <<= 1) {
        for (int j = k >> 1; j > 0; j >>= 1) {
            if (t < EX_CAP) {
                int ixj = t ^ j;
                if (ixj > t) {
                    bool up = ((t & k) == 0);
                    unsigned long long a = extras[t], cc = extras[ixj];
                    if (up ? (a > cc) : (a < cc)) { extras[t] = cc; extras[ixj] = a; }
                }
            }
            __syncthreads();
        }
    }
    if (t < (int)need) dst[base + t] = extras[t];
    __syncthreads();

    // per-bin insertion sort (avg ~2.8 elems/bin)
#pragma unroll
    for (int r = 0; r < FBINS / 1024; r++) {
        unsigned bin = (unsigned)t * (FBINS / 1024) + r;
        if (bin < bstar) {
            unsigned endp  = offs[bin];
            unsigned start = (bin == 0) ? 0u : offs[bin - 1];
            for (unsigned i = start + 1; i < endp; i++) {
                unsigned long long v = dst[i];
                unsigned jj = i;
                while (jj > start && dst[jj - 1] > v) { dst[jj] = dst[jj - 1]; jj--; }
                dst[jj] = v;
            }
        }
    }
    __syncthreads();

    // emit ordered indices; reset counter for next graph replay
    unsigned* sel = &g_sel[(size_t)b * K_];
#pragma unroll
    for (int r = 0; r < K_ / 1024; r++) {
        int j = t + r * 1024;
        sel[j] = (unsigned)(dst[j] & 0x7FFFFull);
    }
    if (t == 0) g_cand_cnt[b] = 0;
}

// ---------------- P3: full-chip gather ----------------
__global__ void k_gather(const float* __restrict__ p, float* __restrict__ out) {
    int j = blockIdx.x * blockDim.x + threadIdx.x;       // one thread = one output point
    int b = j >> 14;                                     // K_ = 2^14
    unsigned idx = g_sel[j];
    const float* src = p + ((size_t)b * N_ + idx) * 3;
    float x = __ldg(src + 0);
    float y = __ldg(src + 1);
    float z = __ldg(src + 2);
    float* dst = out + (size_t)j * 3;
    dst[0] = x; dst[1] = y; dst[2] = z;
}

// ---------------- launch ----------------
extern "C" void kernel_launch(void* const* d_in, const int* in_sizes, int n_in,
                              void* d_out, int out_size) {
    const float* p = (const float*)d_in[0];
    float* out = (float*)d_out;

    // Exact JAX key derivation (threefry, partitionable mode)
    KeysParam kp;
    for (int b = 0; b < B_; b++) {
        unsigned kb0, kb1, s0, s1;
        tf2x32_host(0u, 42u, 0u, (unsigned)b, kb0, kb1);
        tf2x32_host(kb0, kb1, 0u, 0u, s0, s1);
        kp.k[2 * b]     = s0;
        kp.k[2 * b + 1] = s1;
    }
    kp.one = 1u;

    k_main<<<(B_ * N_ / 4) / 256, 256>>>(p, kp);
    cudaFuncSetAttribute(k_order, cudaFuncAttributeMaxDynamicSharedMemorySize,
                         K_ * 8 + FBINS * 4);
    k_order<<<B_, 1024, K_ * 8 + FBINS * 4>>>();
    k_gather<<<(B_ * K_) / 256, 256>>>(p, out);
}

// round 5
// speedup vs baseline: 4.3307x; 1.0003x over previous
#include <cuda_runtime.h>

#define B_ 32
#define N_ 524288          // 2^19 points per batch
#define K_ 16384
#define T_RANK 425984u     // 3.25 * 2^17; E[cand] ~ 18.6k, 17 sigma above K
#define CAP 32768          // per-batch candidate capacity
#define FBINS 8192         // bins: bin = rank>>6 (only bins < 6656 used)
#define EX_CAP 64          // boundary-bin extras capacity (bin ~ Poisson(2.8))

// ---------------- static device scratch (zero-init; kernels restore zeros) ----------------
__device__ int                g_cand_cnt[B_];
__device__ unsigned           g_hist[B_ * FBINS];      // 1 MB, built by k_main
__device__ unsigned long long g_cand[B_ * CAP];        // 8 MB
__device__ unsigned           g_sel [B_ * K_];         // ordered selected indices (2 MB)

struct KeysParam { unsigned k[2 * B_]; };

// ---------------- threefry2x32, 20 rounds (exact JAX partitionable) ----------------
__host__ __device__ __forceinline__ unsigned rotl32(unsigned x, int r) {
#if defined(__CUDA_ARCH__)
    return __funnelshift_l(x, x, r);
#else
    return (x << r) | (x >> (32 - r));
#endif
}

__host__ __device__ __forceinline__ void tf2x32(unsigned k0, unsigned k1,
                                                unsigned x0, unsigned x1,
                                                unsigned& o0, unsigned& o1) {
    unsigned ks2 = k0 ^ k1 ^ 0x1BD11BDAu;
    x0 += k0; x1 += k1;
#define TF_ROUND(r) { x0 += x1; x1 = rotl32(x1, r); x1 ^= x0; }
    TF_ROUND(13) TF_ROUND(15) TF_ROUND(26) TF_ROUND(6)
    x0 += k1;  x1 += ks2 + 1u;
    TF_ROUND(17) TF_ROUND(29) TF_ROUND(16) TF_ROUND(24)
    x0 += ks2; x1 += k0 + 2u;
    TF_ROUND(13) TF_ROUND(15) TF_ROUND(26) TF_ROUND(6)
    x0 += k0;  x1 += k1 + 3u;
    TF_ROUND(17) TF_ROUND(29) TF_ROUND(16) TF_ROUND(24)
    x0 += k1;  x1 += ks2 + 4u;
    TF_ROUND(13) TF_ROUND(15) TF_ROUND(26) TF_ROUND(6)
    x0 += ks2; x1 += k0 + 5u;
#undef TF_ROUND
    o0 = x0; o1 = x1;
}

// ---------------- P1: fused validity + threefry + collect + global histogram ----------------
__global__ void k_main(const float* __restrict__ p, KeysParam keys) {
    __shared__ int s_woff[8];
    __shared__ int s_base;

    unsigned t  = blockIdx.x * blockDim.x + threadIdx.x;   // one thread = 4 points
    unsigned e0 = t * 4u;                                  // block = 1024 consec elems -> one batch
    unsigned b  = e0 >> 19;
    unsigned i0 = e0 & (N_ - 1);

    const float4* pv = reinterpret_cast<const float4*>(p) + (size_t)t * 3;
    float4 v0 = pv[0], v1 = pv[1], v2 = pv[2];
    float c[12] = { v0.x, v0.y, v0.z, v0.w, v1.x, v1.y,
                    v1.z, v1.w, v2.x, v2.y, v2.z, v2.w };

    unsigned k0 = keys.k[2 * b], k1 = keys.k[2 * b + 1];

    unsigned rank[4];
    bool cand[4];
#pragma unroll
    for (int j = 0; j < 4; j++) {
        float s = (c[3 * j] + c[3 * j + 1]) + c[3 * j + 2];   // XLA left-assoc sum
        unsigned a, d;
        tf2x32(k0, k1, 0u, i0 + (unsigned)j, a, d);           // counter (0, i)
        rank[j] = (a ^ d) >> 9;                               // 23-bit rank
        cand[j] = (s != 0.0f) && (rank[j] < T_RANK);
    }

    // ---- hierarchical append: warp ballots -> block reduce -> ONE global atomic ----
    unsigned lane = threadIdx.x & 31u;
    unsigned wid  = threadIdx.x >> 5;                      // 0..7
    unsigned lt_mask = (1u << lane) - 1u;
    unsigned msk[4];
    int tot = 0;
#pragma unroll
    for (int j = 0; j < 4; j++) {
        msk[j] = __ballot_sync(0xFFFFFFFFu, cand[j]);
        tot += __popc(msk[j]);
    }
    if (lane == 0) s_woff[wid] = tot;
    __syncthreads();
    if (threadIdx.x == 0) {
        int sum = 0;
#pragma unroll
        for (int w = 0; w < 8; w++) { int cc = s_woff[w]; s_woff[w] = sum; sum += cc; }
        s_base = atomicAdd(&g_cand_cnt[b], sum);
    }
    __syncthreads();
    int running = s_base + s_woff[wid];
#pragma unroll
    for (int j = 0; j < 4; j++) {
        if (cand[j]) {
            int pos = running + __popc(msk[j] & lt_mask);
            if (pos < CAP)
                g_cand[(size_t)b * CAP + pos] =
                    ((unsigned long long)rank[j] << 19) | (unsigned long long)(i0 + j);
            atomicAdd(&g_hist[b * FBINS + (rank[j] >> 6)], 1u);   // RED, no return
        }
        running += __popc(msk[j]);
    }
}

// ---------------- P2: per-batch exact selection + full ordering (keys only) ----------------
__global__ void k_order() {
    extern __shared__ unsigned char smem_raw[];
    unsigned long long* dst  = reinterpret_cast<unsigned long long*>(smem_raw); // K_ (128KB)
    unsigned*           offs = reinterpret_cast<unsigned*>(dst + K_);           // FBINS (32KB)
    __shared__ unsigned s_wsum[32];
    __shared__ unsigned long long extras[EX_CAP];
    __shared__ int  s_ecnt;
    __shared__ unsigned s_bstar, s_base, s_need;

    int b = blockIdx.x, t = threadIdx.x;                 // 1024 threads
    unsigned lane = t & 31u, wid = t >> 5;
    const unsigned long long* cand = &g_cand[(size_t)b * CAP];
    unsigned* hist = &g_hist[b * FBINS];
    int C = g_cand_cnt[b]; if (C > CAP) C = CAP;

    if (t == 0) s_ecnt = 0;
    // load prebuilt histogram (8 bins/thread, vectorized)
    {
        const uint4* hv = reinterpret_cast<const uint4*>(hist);
        uint4* ov = reinterpret_cast<uint4*>(offs);
        ov[t]        = hv[t];
        ov[t + 1024] = hv[t + 1024];
    }
    __syncthreads();

    // block scan over FBINS (8 bins/thread) via shuffle scan
    unsigned loc[FBINS / 1024], run = 0;
#pragma unroll
    for (int r = 0; r < FBINS / 1024; r++) { loc[r] = run; run += offs[t * (FBINS / 1024) + r]; }
    unsigned wincl = run;
    for (int off = 1; off < 32; off <<= 1) {
        unsigned v = __shfl_up_sync(0xFFFFFFFFu, wincl, off);
        if (lane >= (unsigned)off) wincl += v;
    }
    if (lane == 31u) s_wsum[wid] = wincl;
    __syncthreads();
    if (wid == 0) {
        unsigned v = s_wsum[lane];
        unsigned sc = v;
        for (int off = 1; off < 32; off <<= 1) {
            unsigned u = __shfl_up_sync(0xFFFFFFFFu, sc, off);
            if (lane >= (unsigned)off) sc += u;
        }
        s_wsum[lane] = sc - v;                           // exclusive warp bases
    }
    __syncthreads();
    unsigned incl = wincl + s_wsum[wid];
    unsigned excl = incl - run;

    // exact K-crossing bin
    if (excl < (unsigned)K_ && incl >= (unsigned)K_) {
        unsigned cum = excl;
#pragma unroll
        for (int r = 0; r < FBINS / 1024; r++) {
            unsigned cc = offs[t * (FBINS / 1024) + r];
            if (cum + cc >= (unsigned)K_) {
                s_bstar = (unsigned)(t * (FBINS / 1024) + r);
                s_base  = cum;
                s_need  = (unsigned)K_ - cum;
                break;
            }
            cum += cc;
        }
    }
#pragma unroll
    for (int r = 0; r < FBINS / 1024; r++) offs[t * (FBINS / 1024) + r] = excl + loc[r];
    __syncthreads();

    unsigned bstar = s_bstar, base = s_base, need = s_need;

    // scatter sure-selected, stash boundary-bin extras
    for (int i = t; i < C; i += 1024) {
        unsigned long long key = cand[i];
        unsigned bin = (unsigned)(key >> 25);
        if (bin < bstar) {
            unsigned pos = atomicAdd(&offs[bin], 1u);    // offs -> inclusive prefix
            dst[pos] = key;
        } else if (bin == bstar) {
            int ep = atomicAdd(&s_ecnt, 1);
            if (ep < EX_CAP) extras[ep] = key;
        }
    }
    __syncthreads();

    // warp-0 bitonic sort of 64 extras (2 compares/lane/stage, __syncwarp only)
    if (wid == 0) {
        int ec = s_ecnt; if (ec > EX_CAP) ec = EX_CAP;
        for (int i = lane; i < EX_CAP; i += 32)
            if (i >= ec) extras[i] = 0xFFFFFFFFFFFFFFFFull;
        __syncwarp();
        for (int k = 2; k <= EX_CAP; k <<= 1) {
            for (int j = k >> 1; j > 0; j >>= 1) {
                // 32 compare pairs per stage; lane -> pair index
                unsigned i = ((lane & ~(unsigned)(j - 1)) << 1) | (lane & (unsigned)(j - 1));
                unsigned ixj = i | (unsigned)j;
                bool up = ((i & (unsigned)k) == 0);
                unsigned long long a = extras[i], cc = extras[ixj];
                if (up ? (a > cc) : (a < cc)) { extras[i] = cc; extras[ixj] = a; }
                __syncwarp();
            }
        }
    }
    __syncthreads();
    if (t < (int)need) dst[base + t] = extras[t];
    __syncthreads();

    // per-bin insertion sort (avg ~2.8 elems/bin)
#pragma unroll
    for (int r = 0; r < FBINS / 1024; r++) {
        unsigned bin = (unsigned)t * (FBINS / 1024) + r;
        if (bin < bstar) {
            unsigned endp  = offs[bin];
            unsigned start = (bin == 0) ? 0u : offs[bin - 1];
            for (unsigned i = start + 1; i < endp; i++) {
                unsigned long long v = dst[i];
                unsigned jj = i;
                while (jj > start && dst[jj - 1] > v) { dst[jj] = dst[jj - 1]; jj--; }
                dst[jj] = v;
            }
        }
    }
    __syncthreads();

    // emit ordered indices; reset hist + counter for next graph replay
    unsigned* sel = &g_sel[(size_t)b * K_];
#pragma unroll
    for (int r = 0; r < K_ / 1024; r++) {
        int j = t + r * 1024;
        sel[j] = (unsigned)(dst[j] & 0x7FFFFull);
    }
    {
        uint4 z = make_uint4(0, 0, 0, 0);
        uint4* hv = reinterpret_cast<uint4*>(hist);
        hv[t] = z; hv[t + 1024] = z;
    }
    if (t == 0) g_cand_cnt[b] = 0;
}

// ---------------- P3: full-chip gather, one thread per output float ----------------
__global__ void k_gather(const float* __restrict__ p, float* __restrict__ out) {
    int e = blockIdx.x * blockDim.x + threadIdx.x;       // over 3*B*K floats
    int j = e / 3;                                       // output point
    int c = e - j * 3;                                   // component
    int b = j >> 14;                                     // K_ = 2^14
    unsigned idx = g_sel[j];
    out[e] = __ldg(&p[((size_t)b * N_ + idx) * 3 + c]);
}

// ---------------- launch ----------------
extern "C" void kernel_launch(void* const* d_in, const int* in_sizes, int n_in,
                              void* d_out, int out_size) {
    const float* p = (const float*)d_in[0];
    float* out = (float*)d_out;

    // Exact JAX key derivation (threefry, partitionable mode)
    KeysParam kp;
    for (int b = 0; b < B_; b++) {
        unsigned kb0, kb1, s0, s1;
        tf2x32(0u, 42u, 0u, (unsigned)b, kb0, kb1);
        tf2x32(kb0, kb1, 0u, 0u, s0, s1);
        kp.k[2 * b]     = s0;
        kp.k[2 * b + 1] = s1;
    }

    k_main<<<(B_ * N_ / 4) / 256, 256>>>(p, kp);
    cudaFuncSetAttribute(k_order, cudaFuncAttributeMaxDynamicSharedMemorySize,
                         K_ * 8 + FBINS * 4);
    k_order<<<B_, 1024, K_ * 8 + FBINS * 4>>>();
    k_gather<<<(3 * B_ * K_) / 256, 256>>>(p, out);
}